// round 2
// baseline (speedup 1.0000x reference)
#include <cuda_runtime.h>
#include <math.h>

#define FULLMASK 0xffffffffu

// Hilbert circulant taps (written by init kernel, read uniform via __ldg)
__device__ float g_t[64];
// Per-batch 2x3 matrix M = Ginv * V^T, layout [b][k][c]
__device__ float g_M[3072 * 6];

__global__ void init_t_kernel() {
    int m = threadIdx.x;
    if (m < 64) {
        float v = 0.0f;
        if (m & 1) v = (float)(0.03125 / tan(3.14159265358979323846 * (double)m / 64.0));
        g_t[m] = v;
    }
}

// ---------------------------------------------------------------------------
// Kernel A: per-batch reductions v1,v2 (6 dots of length 12288) + tiny 2x2
// algebra -> M. Weights tiled through smem (48KB) so DRAM traffic = x once.
// One CTA handles 8 batches.
// ---------------------------------------------------------------------------
__global__ __launch_bounds__(256) void reduce_kernel(
    const float* __restrict__ x, const float* __restrict__ w1,
    const float* __restrict__ w2, const float* __restrict__ b1,
    const float* __restrict__ b2) {
    __shared__ float ws[12288];  // [6][2048] weight chunk; reused for reduction
    const int tid = threadIdx.x;
    const int b0 = blockIdx.x * 8;

    float acc[8][6];
#pragma unroll
    for (int i = 0; i < 8; i++)
#pragma unroll
        for (int f = 0; f < 6; f++) acc[i][f] = 0.0f;

    for (int ch = 0; ch < 6; ch++) {
        const int kbase = ch * 2048;
        __syncthreads();
        for (int i = tid; i < 12288; i += 256) {
            int f = i >> 11;
            int kk = i & 2047;
            const float* wsrc = (f < 3) ? w1 : w2;
            int fc = (f < 3) ? f : f - 3;
            ws[i] = __ldg(wsrc + (kbase + kk) * 3 + fc);
        }
        __syncthreads();
#pragma unroll 2
        for (int i = 0; i < 2048; i += 256) {
            int kk = i + tid;
            float wv[6];
#pragma unroll
            for (int f = 0; f < 6; f++) wv[f] = ws[f * 2048 + kk];
            int k = kbase + kk;
#pragma unroll
            for (int bb = 0; bb < 8; bb++) {
                float xv = __ldg(x + (b0 + bb) * 12288 + k);
#pragma unroll
                for (int f = 0; f < 6; f++) acc[bb][f] = fmaf(xv, wv[f], acc[bb][f]);
            }
        }
    }
    __syncthreads();

    const int lane = tid & 31, wid = tid >> 5;
#pragma unroll
    for (int bb = 0; bb < 8; bb++)
#pragma unroll
        for (int f = 0; f < 6; f++) {
            float v = acc[bb][f];
            v += __shfl_down_sync(FULLMASK, v, 16);
            v += __shfl_down_sync(FULLMASK, v, 8);
            v += __shfl_down_sync(FULLMASK, v, 4);
            v += __shfl_down_sync(FULLMASK, v, 2);
            v += __shfl_down_sync(FULLMASK, v, 1);
            if (lane == 0) ws[wid * 48 + bb * 6 + f] = v;
        }
    __syncthreads();
    if (tid < 48) {
        float s = 0.0f;
#pragma unroll
        for (int w = 0; w < 8; w++) s += ws[w * 48 + tid];
        int f = tid % 6;
        s += (f < 3) ? __ldg(b1 + f) : __ldg(b2 + f - 3);
        ws[512 + tid] = s;
    }
    __syncthreads();
    if (tid < 8) {
        float V0[3], V1[3];
        float s0 = 1e-6f, s1 = 1e-6f;
#pragma unroll
        for (int c = 0; c < 3; c++) {
            V0[c] = ws[512 + tid * 6 + c];
            V1[c] = ws[512 + tid * 6 + 3 + c];
            s0 += fabsf(V0[c]);
            s1 += fabsf(V1[c]);
        }
        float r0 = 1.0f / s0, r1 = 1.0f / s1;
        float G00 = 0.f, G01 = 0.f, G11 = 0.f;
#pragma unroll
        for (int c = 0; c < 3; c++) {
            V0[c] *= r0;
            V1[c] *= r1;
            G00 += V0[c] * V0[c];
            G01 += V0[c] * V1[c];
            G11 += V1[c] * V1[c];
        }
        float det = G00 * G11 - G01 * G01;
        float rdet = 1.0f / det;
        float i00 = G11 * rdet, i01 = -G01 * rdet, i11 = G00 * rdet;
        int b = b0 + tid;
#pragma unroll
        for (int c = 0; c < 3; c++) {
            g_M[b * 6 + c]     = i00 * V0[c] + i01 * V1[c];  // k=0 row
            g_M[b * 6 + 3 + c] = i01 * V0[c] + i11 * V1[c];  // k=1 row
        }
    }
}

// ---------------------------------------------------------------------------
// Kernel C: one CTA per output batch g (2048). Builds rec[g] (64 x 192) in
// smem (writing rec channels 0..2 to gmem on the way), then 32-tap circulant
// Hilbert along h via packed fma.rn.f32x2, writing channels 3..5.
// ---------------------------------------------------------------------------
__device__ __forceinline__ unsigned long long pack2(float lo, float hi) {
    unsigned long long r;
    asm("mov.b64 %0, {%1, %2};" : "=l"(r) : "f"(lo), "f"(hi));
    return r;
}
__device__ __forceinline__ void fma2(unsigned long long& d, unsigned long long a,
                                     unsigned long long b) {
    asm("fma.rn.f32x2 %0, %1, %2, %0;" : "+l"(d) : "l"(a), "l"(b));
}
__device__ __forceinline__ void unpack2(unsigned long long v, float& lo, float& hi) {
    asm("mov.b64 {%0, %1}, %2;" : "=f"(lo), "=f"(hi) : "l"(v));
}

__global__ __launch_bounds__(512) void fuse_kernel(const float* __restrict__ x,
                                                   float* __restrict__ out) {
    __shared__ float rec_s[12288];  // [h=64][jp=192]
    const int g = blockIdx.x;
    const int tid = threadIdx.x;
    const int fbase = g * 12288;
    float* outg = out + (size_t)g * 24576;

    // ---- phase 1: rec = M x (regrouped), write to smem + gmem (c<3) ----
#pragma unroll
    for (int it = 0; it < 12; it++) {
        int p = tid + it * 512;   // pair index 0..6143 (j = 2p, 2p+1)
        int f = fbase + 2 * p;
        int b = f >> 13;
        int r = f & 8191;
        int n = r >> 1;
        const float* xp = x + b * 12288 + 3 * n;
        float x0 = __ldg(xp), x1 = __ldg(xp + 1), x2 = __ldg(xp + 2);
        const float* Mb = g_M + b * 6;
        float v0 = __ldg(Mb + 0) * x0 + __ldg(Mb + 1) * x1 + __ldg(Mb + 2) * x2;
        float v1 = __ldg(Mb + 3) * x0 + __ldg(Mb + 4) * x1 + __ldg(Mb + 5) * x2;
        int j = 2 * p;
        rec_s[j] = v0;
        rec_s[j + 1] = v1;
        int h = j / 192;
        int jp = j - h * 192;           // even
        int w0 = jp / 3, c0 = jp - w0 * 3;
        outg[h * 384 + w0 * 6 + c0] = v0;
        int jp1 = jp + 1;
        int w1_ = jp1 / 3, c1 = jp1 - w1_ * 3;
        outg[h * 384 + w1_ * 6 + c1] = v1;
    }
    __syncthreads();

    // ---- phase 2: Hilbert along h. Thread tile: 4 h (stride 16, same
    // parity) x 3 column-pairs. Only opposite-parity h' contribute. ----
    const int tx = tid & 31;
    const int ty = tid >> 5;          // 0..15
    const int jb = 2 * tx;            // base column (pairs jb, jb+1)
    const int hp0 = (ty & 1) ^ 1;     // opposite parity start

    unsigned long long acc[4][3];
#pragma unroll
    for (int m = 0; m < 4; m++)
#pragma unroll
        for (int n = 0; n < 3; n++) acc[m][n] = 0ull;

#pragma unroll 4
    for (int i = 0; i < 32; i++) {
        int h2 = hp0 + 2 * i;
        unsigned long long tm[4];
#pragma unroll
        for (int m = 0; m < 4; m++) {
            float tv = __ldg(&g_t[(ty + 16 * m - h2) & 63]);
            tm[m] = pack2(tv, tv);
        }
        const float* rrow = rec_s + h2 * 192;
#pragma unroll
        for (int n = 0; n < 3; n++) {
            unsigned long long rv =
                *reinterpret_cast<const unsigned long long*>(rrow + jb + 64 * n);
#pragma unroll
            for (int m = 0; m < 4; m++) fma2(acc[m][n], tm[m], rv);
        }
    }

#pragma unroll
    for (int m = 0; m < 4; m++) {
        int h = ty + 16 * m;
#pragma unroll
        for (int n = 0; n < 3; n++) {
            int ja = jb + 64 * n;
            float lo, hi;
            unpack2(acc[m][n], lo, hi);
            int wA = ja / 3, cA = ja - wA * 3;
            outg[h * 384 + wA * 6 + cA + 3] = lo;
            int jb1 = ja + 1;
            int wB = jb1 / 3, cB = jb1 - wB * 3;
            outg[h * 384 + wB * 6 + cB + 3] = hi;
        }
    }
}

extern "C" void kernel_launch(void* const* d_in, const int* in_sizes, int n_in,
                              void* d_out, int out_size) {
    const float* x  = (const float*)d_in[0];
    const float* w1 = (const float*)d_in[1];
    const float* b1 = (const float*)d_in[2];
    const float* w2 = (const float*)d_in[3];
    const float* b2 = (const float*)d_in[4];
    float* out = (float*)d_out;

    init_t_kernel<<<1, 64>>>();
    reduce_kernel<<<384, 256>>>(x, w1, w2, b1, b2);
    fuse_kernel<<<2048, 512>>>(x, out);
}

// round 3
// speedup vs baseline: 1.1391x; 1.1391x over previous
#include <cuda_runtime.h>
#include <math.h>

#define FULLMASK 0xffffffffu

// Per-batch 2x3 matrix M = Ginv * V^T, layout [b][k][c]
__device__ float g_M[3072 * 6];

// ---------------------------------------------------------------------------
// Kernel A: per-batch reductions v1,v2 (6 dots of length 12288) + tiny 2x2
// algebra -> M. Weights tiled through smem so DRAM traffic = x once.
// One CTA handles 8 batches. (unchanged from R1 — validated)
// ---------------------------------------------------------------------------
__global__ __launch_bounds__(256) void reduce_kernel(
    const float* __restrict__ x, const float* __restrict__ w1,
    const float* __restrict__ w2, const float* __restrict__ b1,
    const float* __restrict__ b2) {
    __shared__ float ws[12288];  // [6][2048] weight chunk; reused for reduction
    const int tid = threadIdx.x;
    const int b0 = blockIdx.x * 8;

    float acc[8][6];
#pragma unroll
    for (int i = 0; i < 8; i++)
#pragma unroll
        for (int f = 0; f < 6; f++) acc[i][f] = 0.0f;

    for (int ch = 0; ch < 6; ch++) {
        const int kbase = ch * 2048;
        __syncthreads();
        for (int i = tid; i < 12288; i += 256) {
            int f = i >> 11;
            int kk = i & 2047;
            const float* wsrc = (f < 3) ? w1 : w2;
            int fc = (f < 3) ? f : f - 3;
            ws[i] = __ldg(wsrc + (kbase + kk) * 3 + fc);
        }
        __syncthreads();
#pragma unroll 2
        for (int i = 0; i < 2048; i += 256) {
            int kk = i + tid;
            float wv[6];
#pragma unroll
            for (int f = 0; f < 6; f++) wv[f] = ws[f * 2048 + kk];
            int k = kbase + kk;
#pragma unroll
            for (int bb = 0; bb < 8; bb++) {
                float xv = __ldg(x + (b0 + bb) * 12288 + k);
#pragma unroll
                for (int f = 0; f < 6; f++) acc[bb][f] = fmaf(xv, wv[f], acc[bb][f]);
            }
        }
    }
    __syncthreads();

    const int lane = tid & 31, wid = tid >> 5;
#pragma unroll
    for (int bb = 0; bb < 8; bb++)
#pragma unroll
        for (int f = 0; f < 6; f++) {
            float v = acc[bb][f];
            v += __shfl_down_sync(FULLMASK, v, 16);
            v += __shfl_down_sync(FULLMASK, v, 8);
            v += __shfl_down_sync(FULLMASK, v, 4);
            v += __shfl_down_sync(FULLMASK, v, 2);
            v += __shfl_down_sync(FULLMASK, v, 1);
            if (lane == 0) ws[wid * 48 + bb * 6 + f] = v;
        }
    __syncthreads();
    if (tid < 48) {
        float s = 0.0f;
#pragma unroll
        for (int w = 0; w < 8; w++) s += ws[w * 48 + tid];
        int f = tid % 6;
        s += (f < 3) ? __ldg(b1 + f) : __ldg(b2 + f - 3);
        ws[512 + tid] = s;
    }
    __syncthreads();
    if (tid < 8) {
        float V0[3], V1[3];
        float s0 = 1e-6f, s1 = 1e-6f;
#pragma unroll
        for (int c = 0; c < 3; c++) {
            V0[c] = ws[512 + tid * 6 + c];
            V1[c] = ws[512 + tid * 6 + 3 + c];
            s0 += fabsf(V0[c]);
            s1 += fabsf(V1[c]);
        }
        float r0 = 1.0f / s0, r1 = 1.0f / s1;
        float G00 = 0.f, G01 = 0.f, G11 = 0.f;
#pragma unroll
        for (int c = 0; c < 3; c++) {
            V0[c] *= r0;
            V1[c] *= r1;
            G00 += V0[c] * V0[c];
            G01 += V0[c] * V1[c];
            G11 += V1[c] * V1[c];
        }
        float det = G00 * G11 - G01 * G01;
        float rdet = 1.0f / det;
        float i00 = G11 * rdet, i01 = -G01 * rdet, i11 = G00 * rdet;
        int b = b0 + tid;
#pragma unroll
        for (int c = 0; c < 3; c++) {
            g_M[b * 6 + c]     = i00 * V0[c] + i01 * V1[c];  // k=0 row
            g_M[b * 6 + 3 + c] = i01 * V0[c] + i11 * V1[c];  // k=1 row
        }
    }
}

// ---------------------------------------------------------------------------
// Kernel C: one CTA per output batch g (2048).
// Phase 1: rec = M x (regrouped) into PLANAR smem rec[3][64][PLANE].
// Phase 2: 32-tap circulant Hilbert along h (packed fma.rn.f32x2), then each
//          thread writes two complete 24B output cells per h (STG.128/64).
// ---------------------------------------------------------------------------
typedef unsigned long long ull;
__device__ __forceinline__ ull pack2(float lo, float hi) {
    ull r;
    asm("mov.b64 %0, {%1, %2};" : "=l"(r) : "f"(lo), "f"(hi));
    return r;
}
__device__ __forceinline__ void fma2(ull& d, ull a, ull b) {
    asm("fma.rn.f32x2 %0, %1, %2, %0;" : "+l"(d) : "l"(a), "l"(b));
}
__device__ __forceinline__ void unpack2(ull v, float& lo, float& hi) {
    asm("mov.b64 {%0, %1}, %2;" : "=f"(lo), "=f"(hi) : "l"(v));
}

#define PLANE 4104  // 64*64 + 8 pad: shifts banks by 8 per channel plane

__global__ __launch_bounds__(512) void fuse_kernel(const float* __restrict__ x,
                                                   float* __restrict__ out) {
    __shared__ float rec_s[3 * PLANE];
    __shared__ float ts[64];
    const int g = blockIdx.x;
    const int tid = threadIdx.x;

    if (tid < 64) {
        float v = 0.0f;
        if (tid & 1) {
            float a = 3.14159265358979323846f * (float)tid / 64.0f;
            v = 0.03125f * (cosf(a) / sinf(a));
        }
        ts[tid] = v;
    }

    const int fbase = g * 12288;
    const int b0 = fbase >> 13;
    float M0[6], M1[6];
#pragma unroll
    for (int i = 0; i < 6; i++) {
        M0[i] = __ldg(g_M + b0 * 6 + i);
        M1[i] = __ldg(g_M + (b0 + 1) * 6 + i);
    }

    // ---- phase 1: rec = M x into planar smem ----
#pragma unroll
    for (int it = 0; it < 12; it++) {
        int p = tid + it * 512;     // pair index; elements j=2p, 2p+1
        int f = fbase + 2 * p;
        int b = f >> 13;
        bool useB = (b != b0);
        int n = (f & 8191) >> 1;
        const float* xp = x + b * 12288 + 3 * n;
        float x0 = __ldg(xp), x1 = __ldg(xp + 1), x2 = __ldg(xp + 2);
        float m0 = useB ? M1[0] : M0[0];
        float m1 = useB ? M1[1] : M0[1];
        float m2 = useB ? M1[2] : M0[2];
        float m3 = useB ? M1[3] : M0[3];
        float m4 = useB ? M1[4] : M0[4];
        float m5 = useB ? M1[5] : M0[5];
        float v0 = m0 * x0 + m1 * x1 + m2 * x2;
        float v1 = m3 * x0 + m4 * x1 + m5 * x2;
        int j = 2 * p;
        int h = j / 192;
        int jp = j - h * 192;        // even, same row for j and j+1
        int w = jp / 3, c = jp - w * 3;
        rec_s[c * PLANE + h * 64 + w] = v0;
        int c1 = c + 1, w1 = w;
        if (c1 == 3) { c1 = 0; w1 = w + 1; }
        rec_s[c1 * PLANE + h * 64 + w1] = v1;
    }
    __syncthreads();

    // ---- phase 2: Hilbert along h, f32x2 over w-pairs ----
    const int wp = tid & 31;         // w pair: (2wp, 2wp+1)
    const int ty = tid >> 5;         // 0..15, h = ty + 16m
    const int w0 = 2 * wp;
    const int hp0 = (ty & 1) ^ 1;    // opposite-parity source rows

    ull acc[4][3];
#pragma unroll
    for (int m = 0; m < 4; m++)
#pragma unroll
        for (int n = 0; n < 3; n++) acc[m][n] = 0ull;

#pragma unroll 4
    for (int i = 0; i < 32; i++) {
        int h2 = hp0 + 2 * i;
        ull tm[4];
#pragma unroll
        for (int m = 0; m < 4; m++) {
            float tv = ts[(ty + 16 * m - h2) & 63];
            tm[m] = pack2(tv, tv);
        }
        const float* rrow = rec_s + h2 * 64 + w0;
#pragma unroll
        for (int n = 0; n < 3; n++) {
            ull rv = *reinterpret_cast<const ull*>(rrow + n * PLANE);
#pragma unroll
            for (int m = 0; m < 4; m++) fma2(acc[m][n], tm[m], rv);
        }
    }

    float* outg = out + (size_t)g * 24576;
#pragma unroll
    for (int m = 0; m < 4; m++) {
        int h = ty + 16 * m;
        float r[3][2], a[3][2];
        const float* rrow = rec_s + h * 64 + w0;
#pragma unroll
        for (int n = 0; n < 3; n++) {
            ull rv = *reinterpret_cast<const ull*>(rrow + n * PLANE);
            unpack2(rv, r[n][0], r[n][1]);
            unpack2(acc[m][n], a[n][0], a[n][1]);
        }
        float* pA = outg + h * 384 + w0 * 6;   // 16B aligned (w0 even)
        float4 vA;
        vA.x = r[0][0]; vA.y = r[1][0]; vA.z = r[2][0]; vA.w = a[0][0];
        *reinterpret_cast<float4*>(pA) = vA;
        float2 vA2; vA2.x = a[1][0]; vA2.y = a[2][0];
        *reinterpret_cast<float2*>(pA + 4) = vA2;
        float* pB = pA + 6;                     // 8B aligned
        float2 vB0; vB0.x = r[0][1]; vB0.y = r[1][1];
        float2 vB1; vB1.x = r[2][1]; vB1.y = a[0][1];
        float2 vB2; vB2.x = a[1][1]; vB2.y = a[2][1];
        *reinterpret_cast<float2*>(pB)     = vB0;
        *reinterpret_cast<float2*>(pB + 2) = vB1;
        *reinterpret_cast<float2*>(pB + 4) = vB2;
    }
}

extern "C" void kernel_launch(void* const* d_in, const int* in_sizes, int n_in,
                              void* d_out, int out_size) {
    const float* x  = (const float*)d_in[0];
    const float* w1 = (const float*)d_in[1];
    const float* b1 = (const float*)d_in[2];
    const float* w2 = (const float*)d_in[3];
    const float* b2 = (const float*)d_in[4];
    float* out = (float*)d_out;

    reduce_kernel<<<384, 256>>>(x, w1, w2, b1, b2);
    fuse_kernel<<<2048, 512>>>(x, out);
}